// round 12
// baseline (speedup 1.0000x reference)
#include <cuda_runtime.h>
#include <cstdint>
#include <cstring>

#define NB 256   // batch
#define NPTS 256 // points per side (N == M)
#define ND 4

// per-batch results: [0..NB): eucl_non_zero, [NB..2NB): eucl_zero
__device__ float g_part[2 * NB];
__device__ int   g_count = 0;

static __device__ __forceinline__ uint64_t dup2(float v) {
    uint64_t r; asm("mov.b64 %0, {%1, %1};" : "=l"(r) : "f"(v)); return r;
}
static __device__ __forceinline__ uint64_t ffma2(uint64_t a, uint64_t b, uint64_t c) {
    uint64_t d; asm("fma.rn.f32x2 %0, %1, %2, %3;" : "=l"(d) : "l"(a), "l"(b), "l"(c)); return d;
}
static __device__ __forceinline__ float2 asf2(uint64_t v) {
    float2 f; memcpy(&f, &v, 8); return f;   // register-pair aliasing, no SASS op
}

__global__ __launch_bounds__(256) void chamfer_kernel(
    const float* __restrict__ target,
    const float* __restrict__ reco,
    const int*   __restrict__ in_pid,
    const int*   __restrict__ out_pid,
    float*       __restrict__ out)
{
    // Two pair-interleaved tiles (128 pairs each):
    //  A[p] = { (-2x0,-2x1), (-2y0,-2y1) }, B[p] = comps 2,3
    //  C[p] = ( ||pt0||^2+pen0 , ||pt1||^2+pen1 )
    __shared__ ulonglong2 rTA[NPTS/2], rTB[NPTS/2];  // reco tile (scanned by target rows)
    __shared__ uint64_t   rTC[NPTS/2];
    __shared__ ulonglong2 tTA[NPTS/2], tTB[NPTS/2];  // target tile (scanned by reco rows)
    __shared__ uint64_t   tTC[NPTS/2];
    __shared__ float4     swred[8];
    __shared__ int        s_last;

    const int t = threadIdx.x;
    const int q = t & 127;
    const int lower = (t < 128);   // warps 0-3: target rows/reco tile; 4-7: reco rows/target tile
    const int wid = t >> 5, lane = t & 31;

    int b = blockIdx.x * 2;

    // ---- cold loads for item 0 ----
    const float4* tg4 = (const float4*)(target + (size_t)b * NPTS * ND);
    const float4* rc4 = (const float4*)(reco   + (size_t)b * NPTS * ND);
    const int*    ip  = in_pid  + b * NPTS;
    const int*    op  = out_pid + b * NPTS;
    float4 rv = rc4[t];
    int    rp = op[t];
    float4 tv = tg4[t];
    int    tp = ip[t];

    #pragma unroll 1
    for (int it = 0; it < 2; ++it, ++b) {
        // ---- build both tiles from the prefetched values ----
        {
            int pair = t >> 1, lane2 = t & 1;
            float rn2 = rv.x*rv.x + rv.y*rv.y + rv.z*rv.z + rv.w*rv.w;
            float tn2 = tv.x*tv.x + tv.y*tv.y + tv.z*tv.z + tv.w*tv.w;
            ((float*)rTA)[pair*4 + lane2]     = -2.0f * rv.x;
            ((float*)rTA)[pair*4 + 2 + lane2] = -2.0f * rv.y;
            ((float*)rTB)[pair*4 + lane2]     = -2.0f * rv.z;
            ((float*)rTB)[pair*4 + 2 + lane2] = -2.0f * rv.w;
            ((float*)rTC)[t] = rn2 + (rp != 0 ? 0.0f : 1e20f);
            ((float*)tTA)[pair*4 + lane2]     = -2.0f * tv.x;
            ((float*)tTA)[pair*4 + 2 + lane2] = -2.0f * tv.y;
            ((float*)tTB)[pair*4 + lane2]     = -2.0f * tv.z;
            ((float*)tTB)[pair*4 + 2 + lane2] = -2.0f * tv.w;
            ((float*)tTC)[t] = tn2 + (tp != 0 ? 0.0f : 1e20f);
        }

        // ---- own 2 rows from this half's row source (L1-hot: same lines as tile build) ----
        const float4* row4 = lower ? tg4 : rc4;
        const int*    rpid = lower ? ip  : op;
        float4 v0 = row4[q];
        float4 v1 = row4[q + 128];
        const int m0 = (rpid[q] != 0);
        const int m1 = (rpid[q + 128] != 0);
        const float n20 = v0.x*v0.x + v0.y*v0.y + v0.z*v0.z + v0.w*v0.w;
        const float n21 = v1.x*v1.x + v1.y*v1.y + v1.z*v1.z + v1.w*v1.w;

        const uint64_t r0x = dup2(v0.x), r0y = dup2(v0.y), r0z = dup2(v0.z), r0w = dup2(v0.w);
        const uint64_t r1x = dup2(v1.x), r1y = dup2(v1.y), r1z = dup2(v1.z), r1w = dup2(v1.w);

        // opposite tile (uniform per warp)
        const ulonglong2* SA = lower ? rTA : tTA;
        const ulonglong2* SB = lower ? rTB : tTB;
        const uint64_t*   SC = lower ? rTC : tTC;

        __syncthreads();   // tiles ready

        // ---- prefetch next item's gmem NOW (latency hides under mainloop) ----
        if (it == 0) {
            tg4 = (const float4*)(target + (size_t)(b+1) * NPTS * ND);
            rc4 = (const float4*)(reco   + (size_t)(b+1) * NPTS * ND);
            ip  = in_pid  + (b+1) * NPTS;
            op  = out_pid + (b+1) * NPTS;
            rv = rc4[t];
            rp = op[t];
            tv = tg4[t];
            tp = ip[t];
        }

        // ---- main loop: 128 pair-iters, 2 rows -> 4 dist/iter ----
        float dlo0 = 3.0e38f, dhi0 = 3.0e38f, dlo1 = 3.0e38f, dhi1 = 3.0e38f;
        #pragma unroll 8
        for (int m = 0; m < NPTS/2; ++m) {
            ulonglong2 A = SA[m];      // broadcast LDS.128
            ulonglong2 B = SB[m];      // broadcast LDS.128
            uint64_t   c = SC[m];      // broadcast LDS.64

            uint64_t s0 = ffma2(A.x, r0x, c);
            uint64_t s1 = ffma2(A.x, r1x, c);
            s0 = ffma2(A.y, r0y, s0);
            s1 = ffma2(A.y, r1y, s1);
            s0 = ffma2(B.x, r0z, s0);
            s1 = ffma2(B.x, r1z, s1);
            s0 = ffma2(B.y, r0w, s0);
            s1 = ffma2(B.y, r1w, s1);

            float2 f0 = asf2(s0), f1 = asf2(s1);
            dlo0 = fminf(dlo0, f0.x); dhi0 = fminf(dhi0, f0.y);
            dlo1 = fminf(dlo1, f1.x); dhi1 = fminf(dhi1, f1.y);
        }
        // add row-norm (constant over tile), clamp cancellation negatives
        float d20 = fmaxf(fminf(dlo0, dhi0) + n20, 0.0f);
        float d21 = fmaxf(fminf(dlo1, dhi1) + n21, 0.0f);

        float sum_min = (m0 ? sqrtf(d20) : 0.0f) + (m1 ? sqrtf(d21) : 0.0f);
        float na = sqrtf(n20), nb2 = sqrtf(n21);
        float sum_nrm = lower ? ((m0 ? na : 0.0f) + (m1 ? nb2 : 0.0f))    // sum ||x|| over mask_x
                              : ((m0 ? 0.0f : na) + (m1 ? 0.0f : nb2));   // sum ||y|| over ~mask_y
        float cnt = (float)(m0 + m1);  // nx (lower) / ny (upper)

        // ---- warp shfl reduce ----
        #pragma unroll
        for (int off = 16; off > 0; off >>= 1) {
            sum_min += __shfl_xor_sync(0xffffffffu, sum_min, off);
            sum_nrm += __shfl_xor_sync(0xffffffffu, sum_nrm, off);
            cnt     += __shfl_xor_sync(0xffffffffu, cnt, off);
        }
        if (lane == 0) swred[wid] = make_float4(sum_min, sum_nrm, cnt, 0.0f);
        __syncthreads();

        // ---- thread 0: combine both phases, final per-batch outputs ----
        if (t == 0) {
            float sum_xy = 0.0f, sum_nrmx = 0.0f, fnx = 0.0f;
            float sum_yx = 0.0f, sum_nrmy0 = 0.0f, fny = 0.0f;
            #pragma unroll
            for (int w = 0; w < 4; ++w) {
                float4 r = swred[w];
                sum_xy += r.x; sum_nrmx += r.y; fnx += r.z;
            }
            #pragma unroll
            for (int w = 4; w < 8; ++w) {
                float4 r = swred[w];
                sum_yx += r.x; sum_nrmy0 += r.y; fny += r.z;
            }
            float n_in  = fmaxf(1.0f, fnx);
            float n_out = fmaxf(1.0f, fny);
            float normal = 0.5f * (sum_xy / n_out + sum_yx / n_in);
            float e_nz = (fny == 0.0f) ? (sum_nrmx / n_in)
                       : ((fnx == 0.0f) ? 0.0f : normal);
            float e_z  = sum_nrmy0 / fmaxf(1.0f, (float)NPTS - fny);
            g_part[b]      = e_nz;
            g_part[NB + b] = e_z;
        }
        __syncthreads();   // protect smem tiles before next item overwrites
    }

    // ---- one handshake per block ----
    if (t == 0) {
        __threadfence();
        int old = atomicAdd(&g_count, 1);
        s_last = (old == NB/2 - 1);
    }
    __syncthreads();

    // ---- last block: mean over batches (1 batch per thread) ----
    if (s_last) {
        if (t == 0) { g_count = 0; __threadfence(); }
        float e0 = __ldcg(&g_part[t]);
        float e1 = __ldcg(&g_part[NB + t]);
        #pragma unroll
        for (int off = 16; off > 0; off >>= 1) {
            e0 += __shfl_xor_sync(0xffffffffu, e0, off);
            e1 += __shfl_xor_sync(0xffffffffu, e1, off);
        }
        if (lane == 0) swred[wid] = make_float4(e0, e1, 0.0f, 0.0f);
        __syncthreads();
        if (t == 0) {
            float a = 0.0f, b2 = 0.0f;
            #pragma unroll
            for (int w = 0; w < 8; ++w) { a += swred[w].x; b2 += swred[w].y; }
            out[0] = a * (1.0f / NB);
            out[1] = b2 * (1.0f / NB);
        }
    }
}

extern "C" void kernel_launch(void* const* d_in, const int* in_sizes, int n_in,
                              void* d_out, int out_size)
{
    const float* target  = (const float*)d_in[0];
    const float* reco    = (const float*)d_in[1];
    const int*   in_pid  = (const int*)d_in[2];
    const int*   out_pid = (const int*)d_in[3];
    float* out = (float*)d_out;

    chamfer_kernel<<<NB/2, 256>>>(target, reco, in_pid, out_pid, out);
}

// round 13
// speedup vs baseline: 1.1379x; 1.1379x over previous
#include <cuda_runtime.h>
#include <cstdint>
#include <cstring>

#define NB 256   // batch
#define NPTS 256 // points per side (N == M)
#define ND 4

// per-batch partials: [0]=sum_xy [1]=sum_nrmx [2]=nx [3]=sum_yx [4]=sum_nrmy0 [5]=ny
__device__ float g_sc[6 * NB];
__device__ int   g_count = 0;

static __device__ __forceinline__ uint64_t dup2(float v) {
    uint64_t r; asm("mov.b64 %0, {%1, %1};" : "=l"(r) : "f"(v)); return r;
}
static __device__ __forceinline__ uint64_t ffma2(uint64_t a, uint64_t b, uint64_t c) {
    uint64_t d; asm("fma.rn.f32x2 %0, %1, %2, %3;" : "=l"(d) : "l"(a), "l"(b), "l"(c)); return d;
}
static __device__ __forceinline__ float2 asf2(uint64_t v) {
    float2 f; memcpy(&f, &v, 8); return f;   // register-pair aliasing, no SASS op
}

__global__ __launch_bounds__(128, 4) void chamfer_kernel(
    const float* __restrict__ target,
    const float* __restrict__ reco,
    const int*   __restrict__ in_pid,
    const int*   __restrict__ out_pid,
    float*       __restrict__ out)
{
    // Full tile (256 pts = 128 pairs), pair-interleaved for f32x2:
    //  sA[p] = { (-2x_e0,-2x_e1), (-2y_e0,-2y_e1) }, sB = comps 2,3
    //  sc[p] = ( ||pt0||^2+pen0 , ||pt1||^2+pen1 )
    __shared__ ulonglong2 sA[NPTS/2], sB[NPTS/2];
    __shared__ uint64_t   sc[NPTS/2];
    __shared__ float      spm[4 * NPTS];   // partial row-mins per tile-quarter
    __shared__ float      srn2[NPTS];      // ||row||^2
    __shared__ int        smask[NPTS];     // row pid != 0
    __shared__ float4     swred[4];
    __shared__ int        s_last;

    const int bid   = blockIdx.x;
    const int b     = bid >> 1;
    const int phase = bid & 1;     // 0: rows=target, tile=reco ; 1: rows=reco, tile=target
    const int t     = threadIdx.x;
    const int g     = t >> 5;      // tile quarter this thread scans
    const int l5    = t & 31;      // row base lane

    const float* tileSrc = phase == 0 ? reco    : target;
    const int*   tilePid = phase == 0 ? out_pid : in_pid;
    const float* rowSrc  = phase == 0 ? target  : reco;
    const int*   rowPid  = phase == 0 ? in_pid  : out_pid;

    const float4* tile4 = (const float4*)(tileSrc + (size_t)b * NPTS * ND);
    const float4* row4  = (const float4*)(rowSrc  + (size_t)b * NPTS * ND);
    const int*    tpid  = tilePid + b * NPTS;
    const int*    rpid  = rowPid  + b * NPTS;

    // ---- build tile (2 points per thread) ----
    #pragma unroll
    for (int k = 0; k < 2; ++k) {
        int i = t + k * 128;
        float4 v = tile4[i];
        int pid  = tpid[i];
        float n2 = v.x*v.x + v.y*v.y + v.z*v.z + v.w*v.w;
        int pair = i >> 1, lane = i & 1;
        ((float*)sA)[pair*4 + lane]     = -2.0f * v.x;
        ((float*)sA)[pair*4 + 2 + lane] = -2.0f * v.y;
        ((float*)sB)[pair*4 + lane]     = -2.0f * v.z;
        ((float*)sB)[pair*4 + 2 + lane] = -2.0f * v.w;
        ((float*)sc)[i] = n2 + (pid != 0 ? 0.0f : 1e20f);
    }

    // ---- own 8 rows: row = l5 + 32k (coalesced per k; all 4 groups load same rows) ----
    uint64_t rx[8], ry[8], rz[8], rw[8];
    #pragma unroll
    for (int k = 0; k < 8; ++k) {
        int row = l5 + 32 * k;
        float4 v = row4[row];
        rx[k] = dup2(v.x); ry[k] = dup2(v.y); rz[k] = dup2(v.z); rw[k] = dup2(v.w);
        if (g == 0) {
            srn2[row]  = v.x*v.x + v.y*v.y + v.z*v.z + v.w*v.w;
            smask[row] = (rpid[row] != 0);
        }
    }

    __syncthreads();

    // ---- main loop: 32 pair-iters over this thread's tile quarter, 8 rows -> 16 dist/iter ----
    float dlo[8], dhi[8];
    #pragma unroll
    for (int k = 0; k < 8; ++k) { dlo[k] = 3.0e38f; dhi[k] = 3.0e38f; }
    const int mbase = g * 32;
    #pragma unroll 4
    for (int mm = 0; mm < 32; ++mm) {
        int m = mbase + mm;
        ulonglong2 A = sA[m];      // broadcast LDS.128
        ulonglong2 B = sB[m];      // broadcast LDS.128
        uint64_t   c = sc[m];      // broadcast LDS.64

        uint64_t s[8];
        #pragma unroll
        for (int k = 0; k < 8; ++k) s[k] = ffma2(A.x, rx[k], c);
        #pragma unroll
        for (int k = 0; k < 8; ++k) s[k] = ffma2(A.y, ry[k], s[k]);
        #pragma unroll
        for (int k = 0; k < 8; ++k) s[k] = ffma2(B.x, rz[k], s[k]);
        #pragma unroll
        for (int k = 0; k < 8; ++k) s[k] = ffma2(B.y, rw[k], s[k]);
        #pragma unroll
        for (int k = 0; k < 8; ++k) {
            float2 f = asf2(s[k]);
            dlo[k] = fminf(dlo[k], f.x);
            dhi[k] = fminf(dhi[k], f.y);
        }
    }

    // ---- store partial mins for this quarter ----
    #pragma unroll
    for (int k = 0; k < 8; ++k)
        spm[g * NPTS + l5 + 32 * k] = fminf(dlo[k], dhi[k]);
    __syncthreads();

    // ---- combine quarters: thread t handles rows t and t+128 ----
    float sum_min = 0.0f, sum_nrm = 0.0f, cnt = 0.0f;
    #pragma unroll
    for (int k = 0; k < 2; ++k) {
        int row = t + 128 * k;
        float d = fminf(fminf(spm[row], spm[NPTS + row]),
                        fminf(spm[2*NPTS + row], spm[3*NPTS + row]));
        float n2r = srn2[row];
        int   mr  = smask[row];
        float dd = fmaxf(d + n2r, 0.0f);      // clamp cancellation negatives
        sum_min += mr ? sqrtf(dd) : 0.0f;
        float nr = sqrtf(n2r);
        sum_nrm += (phase == 0) ? (mr ? nr : 0.0f)   // sum ||x|| over mask_x
                                : (mr ? 0.0f : nr);  // sum ||y|| over ~mask_y
        cnt += (float)mr;
    }

    // ---- warp shfl reduce, then cross-warp ----
    #pragma unroll
    for (int off = 16; off > 0; off >>= 1) {
        sum_min += __shfl_xor_sync(0xffffffffu, sum_min, off);
        sum_nrm += __shfl_xor_sync(0xffffffffu, sum_nrm, off);
        cnt     += __shfl_xor_sync(0xffffffffu, cnt, off);
    }
    const int wid = t >> 5, lane = t & 31;
    if (lane == 0) swred[wid] = make_float4(sum_min, sum_nrm, cnt, 0.0f);
    __syncthreads();

    if (t == 0) {
        float a = 0.0f, b2 = 0.0f, c2 = 0.0f;
        #pragma unroll
        for (int w = 0; w < 4; ++w) {
            float4 r = swred[w];
            a += r.x; b2 += r.y; c2 += r.z;
        }
        g_sc[(phase*3 + 0) * NB + b] = a;
        g_sc[(phase*3 + 1) * NB + b] = b2;
        g_sc[(phase*3 + 2) * NB + b] = c2;
        __threadfence();
        int old = atomicAdd(&g_count, 1);
        s_last = (old == 2*NB - 1);
    }
    __syncthreads();

    // ---- last block: fused finalize (2 batches per thread) ----
    if (s_last) {
        if (t == 0) { g_count = 0; __threadfence(); }
        __syncthreads();
        float acc0 = 0.0f, acc1 = 0.0f;
        #pragma unroll
        for (int k = 0; k < 2; ++k) {
            int bb = t + k * 128;
            float sum_xy    = __ldcg(&g_sc[0*NB + bb]);
            float sum_nrmx  = __ldcg(&g_sc[1*NB + bb]);
            float fnx       = __ldcg(&g_sc[2*NB + bb]);
            float sum_yx    = __ldcg(&g_sc[3*NB + bb]);
            float sum_nrmy0 = __ldcg(&g_sc[4*NB + bb]);
            float fny       = __ldcg(&g_sc[5*NB + bb]);
            float n_in  = fmaxf(1.0f, fnx);
            float n_out = fmaxf(1.0f, fny);
            float normal = 0.5f * (sum_xy / n_out + sum_yx / n_in);
            float e_nz = (fny == 0.0f) ? (sum_nrmx / n_in)
                       : ((fnx == 0.0f) ? 0.0f : normal);
            float e_z  = sum_nrmy0 / fmaxf(1.0f, (float)NPTS - fny);
            acc0 += e_nz;
            acc1 += e_z;
        }
        #pragma unroll
        for (int off = 16; off > 0; off >>= 1) {
            acc0 += __shfl_xor_sync(0xffffffffu, acc0, off);
            acc1 += __shfl_xor_sync(0xffffffffu, acc1, off);
        }
        if (lane == 0) swred[wid] = make_float4(acc0, acc1, 0.0f, 0.0f);
        __syncthreads();
        if (t == 0) {
            float a = 0.0f, b2 = 0.0f;
            #pragma unroll
            for (int w = 0; w < 4; ++w) { a += swred[w].x; b2 += swred[w].y; }
            out[0] = a * (1.0f / NB);
            out[1] = b2 * (1.0f / NB);
        }
    }
}

extern "C" void kernel_launch(void* const* d_in, const int* in_sizes, int n_in,
                              void* d_out, int out_size)
{
    const float* target  = (const float*)d_in[0];
    const float* reco    = (const float*)d_in[1];
    const int*   in_pid  = (const int*)d_in[2];
    const int*   out_pid = (const int*)d_in[3];
    float* out = (float*)d_out;

    chamfer_kernel<<<2 * NB, 128>>>(target, reco, in_pid, out_pid, out);
}